// round 2
// baseline (speedup 1.0000x reference)
#include <cuda_runtime.h>
#include <cstdint>
#include <cstddef>

#define NMAX   500000
#define GQ     128
#define GCELLS (2*GQ*GQ*GQ)
#define KTOP   256
#define NBINS  4096
#define CANDMAX 4096

// ------------------------- scratch (__device__ globals, no allocs) ---------
__device__ int                 g_grid[GCELLS];
__device__ int                 g_owner[NMAX];
__device__ unsigned char       g_peak[NMAX];
__device__ int                 g_hist[NBINS];
__device__ int                 g_thresh;
__device__ int                 g_candcnt;
__device__ int                 g_touchcnt;
__device__ unsigned long long  g_ckey[CANDMAX];
__device__ float               g_conf[KTOP];
__device__ int                 g_topidx[KTOP];
__device__ int                 g_touched[2048];
__device__ float               g_sums[KTOP*128];
__device__ float               g_counts[KTOP];
__device__ float               g_cols[257*32];

// packed f32x2 FMA (FFMA2) -------------------------------------------------
union F2 { unsigned long long u; float2 f; };

__device__ __forceinline__ void ffma2(unsigned long long& d,
                                      unsigned long long a,
                                      unsigned long long b)
{
    asm("fma.rn.f32x2 %0, %1, %2, %0;" : "+l"(d) : "l"(a), "l"(b));
}

// ------------------------- clear ------------------------------------------
__global__ void k_clear(int n)
{
    int i = blockIdx.x * blockDim.x + threadIdx.x;
    if (i < GCELLS) g_grid[i] = -1;
    if (i < NMAX)   g_owner[i] = -1;
    if (i < NBINS)  g_hist[i]  = 0;
    if (i < KTOP*128) g_sums[i] = 0.0f;
    if (i < KTOP)   g_counts[i] = 0.0f;
    if (i == 0) { g_candcnt = 0; g_touchcnt = 0; }
}

// ------------------------- fill grid --------------------------------------
__global__ void k_fill(const int* __restrict__ coords, int n)
{
    int i = blockIdx.x * blockDim.x + threadIdx.x;
    if (i >= n) return;
    int4 c = ((const int4*)coords)[i];
    int cell = ((c.x * GQ + c.y) * GQ + c.z) * GQ + c.w;
    g_grid[cell] = i;
}

// ------------------------- peak detection + histogram ---------------------
__global__ void k_peaks(const int* __restrict__ coords,
                        const float* __restrict__ scores, int n)
{
    int i = blockIdx.x * blockDim.x + threadIdx.x;
    if (i >= n) return;
    float s = scores[i];
    bool pk = false;
    if (s > 0.1f) {
        float nm = -1e30f;
        int4 c = ((const int4*)coords)[i];
        const int dx[7] = {0, 1,-1, 0, 0, 0, 0};
        const int dy[7] = {0, 0, 0, 1,-1, 0, 0};
        const int dz[7] = {0, 0, 0, 0, 0, 1,-1};
        #pragma unroll
        for (int o = 0; o < 7; ++o) {
            int nx = c.y + dx[o], ny = c.z + dy[o], nz = c.w + dz[o];
            if (nx < 0 || nx >= GQ || ny < 0 || ny >= GQ || nz < 0 || nz >= GQ) continue;
            int cell = ((c.x * GQ + nx) * GQ + ny) * GQ + nz;
            int j = g_grid[cell];
            if (j >= 0) {
                float sj = scores[j];
                if (sj > 0.1f) nm = fmaxf(nm, sj);
            }
        }
        pk = (s >= nm - 1e-6f) && (s >= 0.5f);
    }
    g_peak[i] = pk ? 1 : 0;
    if (pk) {
        int b = (int)((s - 0.5f) * 8192.0f);
        b = b < 0 ? 0 : (b > NBINS-1 ? NBINS-1 : b);
        atomicAdd(&g_hist[b], 1);
    }
}

// ------------------------- threshold scan (1 block, 256 thr) --------------
__global__ void k_scan()
{
    __shared__ int h[NBINS];
    __shared__ int sup[64];
    int t = threadIdx.x;
    for (int i = t; i < NBINS; i += 256) h[i] = g_hist[i];
    __syncthreads();
    if (t < 64) {
        int s = 0;
        for (int m = 0; m < 64; ++m) s += h[t*64 + m];
        sup[t] = s;
    }
    __syncthreads();
    if (t == 0) {
        int total = 0;
        for (int s = 0; s < 64; ++s) total += sup[s];
        int target = total < KTOP ? total : KTOP;
        int T = 0;
        if (target > 0) {
            int acc = 0, sb = 63;
            for (; sb >= 0; --sb) {
                if (acc + sup[sb] >= target) break;
                acc += sup[sb];
            }
            for (int b = 63; b >= 0; --b) {
                acc += h[sb*64 + b];
                if (acc >= target) { T = sb*64 + b; break; }
            }
        }
        g_thresh = T;
    }
}

// ------------------------- collect candidates -----------------------------
__global__ void k_collect(const float* __restrict__ scores, int n)
{
    int i = blockIdx.x * blockDim.x + threadIdx.x;
    if (i >= n || !g_peak[i]) return;
    float s = scores[i];
    int b = (int)((s - 0.5f) * 8192.0f);
    b = b < 0 ? 0 : (b > NBINS-1 ? NBINS-1 : b);
    if (b >= g_thresh) {
        int pos = atomicAdd(&g_candcnt, 1);
        if (pos < CANDMAX) {
            unsigned long long key =
                ((unsigned long long)__float_as_uint(s) << 32)
              | (unsigned long long)(0xFFFFFFFFu - (unsigned)i);
            g_ckey[pos] = key;
        }
    }
}

// ------------------------- bitonic top-256 (1 block, 1024 thr) ------------
__global__ void k_sort(float* conf_out)
{
    __shared__ unsigned long long sk[CANDMAX];
    int t = threadIdx.x;
    int cnt = g_candcnt;
    if (cnt > CANDMAX) cnt = CANDMAX;
    for (int i = t; i < CANDMAX; i += 1024)
        sk[i] = (i < cnt) ? g_ckey[i] : 0ULL;
    __syncthreads();
    for (int k = 2; k <= CANDMAX; k <<= 1) {
        for (int j = k >> 1; j > 0; j >>= 1) {
            for (int i = t; i < CANDMAX; i += 1024) {
                int ixj = i ^ j;
                if (ixj > i) {
                    unsigned long long a = sk[i], b = sk[ixj];
                    bool sw = ((i & k) == 0) ? (a < b) : (a > b);
                    if (sw) { sk[i] = b; sk[ixj] = a; }
                }
            }
            __syncthreads();
        }
    }
    if (t < KTOP) {
        bool valid = t < cnt;
        unsigned long long key = sk[t];
        float sc = valid ? __uint_as_float((unsigned)(key >> 32)) : 0.0f;
        g_conf[t] = sc;
        g_topidx[t] = valid ? (int)(0xFFFFFFFFu - (unsigned)(key & 0xFFFFFFFFULL)) : -1;
        if (conf_out) conf_out[t] = sc;
    }
}

// ------------------------- owner assignment (1 block, 256 thr) ------------
__global__ void k_owner(const int* __restrict__ coords,
                        const float* __restrict__ scores)
{
    int k = threadIdx.x;
    if (k >= KTOP) return;
    int p = g_topidx[k];
    if (p < 0) return;
    int4 c = ((const int4*)coords)[p];
    const int dx[7] = {0, 1,-1, 0, 0, 0, 0};
    const int dy[7] = {0, 0, 0, 1,-1, 0, 0};
    const int dz[7] = {0, 0, 0, 0, 0, 1,-1};
    #pragma unroll
    for (int o = 0; o < 7; ++o) {
        int nx = c.y + dx[o], ny = c.z + dy[o], nz = c.w + dz[o];
        if (nx < 0 || nx >= GQ || ny < 0 || ny >= GQ || nz < 0 || nz >= GQ) continue;
        int cell = ((c.x * GQ + nx) * GQ + ny) * GQ + nz;
        int j = g_grid[cell];
        if (j >= 0 && scores[j] > 0.1f) {
            int old = atomicMax(&g_owner[j], k);
            if (old == -1) {
                int pos = atomicAdd(&g_touchcnt, 1);
                g_touched[pos] = j;
            }
        }
    }
}

// ------------------------- segment sums (1792 blocks x 128) ---------------
__global__ void k_segsum(const float* __restrict__ feats)
{
    if ((int)blockIdx.x >= g_touchcnt) return;
    int i = g_touched[blockIdx.x];
    int o = g_owner[i];
    atomicAdd(&g_sums[o*128 + threadIdx.x], feats[(size_t)i*128 + threadIdx.x]);
    if (threadIdx.x == 0) atomicAdd(&g_counts[o], 1.0f);
}

// ------------------------- build cols (257 blocks x 128) ------------------
__global__ void k_cols(const float* __restrict__ Wc,
                       const float* __restrict__ bc,
                       const float* __restrict__ bg)
{
    int k = blockIdx.x;
    int t = threadIdx.x;
    if (k == 0) {
        if (t < 32) g_cols[t] = bg[t];
        return;
    }
    int seg = k - 1;
    __shared__ float mean[128];
    float cnt = fmaxf(g_counts[seg], 1.0f);
    mean[t] = g_sums[seg*128 + t] / cnt;
    __syncthreads();
    if (t < 32) {
        float a = bc[t];
        #pragma unroll 8
        for (int m = 0; m < 128; ++m) a += mean[m] * Wc[m*32 + t];
        g_cols[k*32 + t] = g_conf[seg] * a;
    }
}

// ------------------------- fused dense GEMM (FFMA2 version) ---------------
// Stage 1: desc = A@Wv + bv (128-row tile x 32)
// Stage 2: out  = desc @ cols^T (x 257)
//
// smem plan (floats):
//   stage1: sA    [64][132] @ 0      (8448)   A k-slice, transposed [k][r]
//           sWv2  [128][64] @ 8448   (8192)   Wv duplicated pairs (w,w)
//   stage2: sC2   [32][520] @ 0      (16640)  colsT duplicated pairs (reuses sA+sWv2)
//   both:   sD    [32][132] @ 16640  (4224)   descT [d][r]
//           sbv           @ 20864   (32)
#define SM_A    0
#define SM_WV2  8448
#define SM_C2   0
#define SM_D    16640
#define SM_BV   20864
#define SM_FLTS 20896

__global__ void __launch_bounds__(256, 2)
k_main(const float* __restrict__ A, const float* __restrict__ Wv,
       const float* __restrict__ bv, float* __restrict__ outI, int n)
{
    extern __shared__ float sm[];
    float* sA   = sm + SM_A;
    float* sWv2 = sm + SM_WV2;
    float* sC2  = sm + SM_C2;
    float* sD   = sm + SM_D;
    float* sbv  = sm + SM_BV;

    int t = threadIdx.x;
    int row0 = blockIdx.x * 128;
    int rg = t >> 3;     // 0..31 -> rows 4rg..4rg+3
    int dg = t & 7;      // 0..7  -> d/c group 4dg..4dg+3

    // preload Wv duplicated: sWv2[k*64 + 2d] = sWv2[k*64+2d+1] = Wv[k*32+d]
    for (int i = t; i < 4096; i += 256) {
        int k = i >> 5, d = i & 31;
        float w = Wv[i];
        sWv2[k*64 + 2*d]     = w;
        sWv2[k*64 + 2*d + 1] = w;
    }
    if (t < 32) sbv[t] = bv[t];

    // ---------------- stage 1: desc = A @ Wv + bv ----------------
    F2 acc[2][4];
    #pragma unroll
    for (int p = 0; p < 2; ++p)
        #pragma unroll
        for (int j = 0; j < 4; ++j) acc[p][j].f = make_float2(0.f, 0.f);

    for (int sl = 0; sl < 2; ++sl) {
        __syncthreads();
        // load 128 rows x 64-k slice, transposed into sA[k][r] (stride 132)
        #pragma unroll
        for (int it = 0; it < 8; ++it) {
            int idx = t + 256*it;        // float4 unit id, 0..2047
            int r = idx >> 4, q = idx & 15;
            int grow = row0 + r;
            float4 v = make_float4(0.f, 0.f, 0.f, 0.f);
            if (grow < n)
                v = *(const float4*)(A + (size_t)grow*128 + sl*64 + 4*q);
            sA[(4*q+0)*132 + r] = v.x;
            sA[(4*q+1)*132 + r] = v.y;
            sA[(4*q+2)*132 + r] = v.z;
            sA[(4*q+3)*132 + r] = v.w;
        }
        __syncthreads();
        #pragma unroll 8
        for (int kk = 0; kk < 64; ++kk) {
            int k = sl*64 + kk;
            // row pairs (4rg,4rg+1) and (4rg+2,4rg+3)
            ulonglong2 av = *(const ulonglong2*)(sA + kk*132 + 4*rg);
            // duplicated weights for d = 4dg..4dg+3
            ulonglong2 w0 = *(const ulonglong2*)(sWv2 + k*64 + 8*dg);
            ulonglong2 w1 = *(const ulonglong2*)(sWv2 + k*64 + 8*dg + 4);
            ffma2(acc[0][0].u, av.x, w0.x);
            ffma2(acc[0][1].u, av.x, w0.y);
            ffma2(acc[0][2].u, av.x, w1.x);
            ffma2(acc[0][3].u, av.x, w1.y);
            ffma2(acc[1][0].u, av.y, w0.x);
            ffma2(acc[1][1].u, av.y, w0.y);
            ffma2(acc[1][2].u, av.y, w1.x);
            ffma2(acc[1][3].u, av.y, w1.y);
        }
    }
    // write descT[d][r] (stride 132), add bias
    #pragma unroll
    for (int j = 0; j < 4; ++j) {
        float b = sbv[4*dg + j];
        float2 lo = make_float2(acc[0][j].f.x + b, acc[0][j].f.y + b);
        float2 hi = make_float2(acc[1][j].f.x + b, acc[1][j].f.y + b);
        *(float2*)(sD + (4*dg + j)*132 + 4*rg)     = lo;
        *(float2*)(sD + (4*dg + j)*132 + 4*rg + 2) = hi;
    }
    __syncthreads();

    // load duplicated colsT into sC2[k][2c],[2c+1]  (overwrites sA/sWv2)
    for (int i = t; i < 257*32; i += 256) {
        int c = i >> 5, k = i & 31;
        float w = g_cols[i];
        sC2[k*520 + 2*c]     = w;
        sC2[k*520 + 2*c + 1] = w;
    }
    __syncthreads();

    // ---------------- stage 2: out = desc @ cols^T ----------------
    int cg = dg;
    for (int cb = 0; cb < 256; cb += 32) {
        F2 o[2][4];
        #pragma unroll
        for (int p = 0; p < 2; ++p)
            #pragma unroll
            for (int j = 0; j < 4; ++j) o[p][j].f = make_float2(0.f, 0.f);
        #pragma unroll 8
        for (int k = 0; k < 32; ++k) {
            ulonglong2 dv = *(const ulonglong2*)(sD + k*132 + 4*rg);
            ulonglong2 w0 = *(const ulonglong2*)(sC2 + k*520 + 2*cb + 8*cg);
            ulonglong2 w1 = *(const ulonglong2*)(sC2 + k*520 + 2*cb + 8*cg + 4);
            ffma2(o[0][0].u, dv.x, w0.x);
            ffma2(o[0][1].u, dv.x, w0.y);
            ffma2(o[0][2].u, dv.x, w1.x);
            ffma2(o[0][3].u, dv.x, w1.y);
            ffma2(o[1][0].u, dv.y, w0.x);
            ffma2(o[1][1].u, dv.y, w0.y);
            ffma2(o[1][2].u, dv.y, w1.x);
            ffma2(o[1][3].u, dv.y, w1.y);
        }
        // unpack: pair element x -> row 4rg+2p, y -> row 4rg+2p+1
        #pragma unroll
        for (int p = 0; p < 2; ++p) {
            int r0 = row0 + 4*rg + 2*p;
            if (r0 < n) {
                float* op = outI + (size_t)r0*257 + cb + 4*cg;
                op[0] = o[p][0].f.x; op[1] = o[p][1].f.x;
                op[2] = o[p][2].f.x; op[3] = o[p][3].f.x;
            }
            if (r0 + 1 < n) {
                float* op = outI + (size_t)(r0+1)*257 + cb + 4*cg;
                op[0] = o[p][0].f.y; op[1] = o[p][1].f.y;
                op[2] = o[p][2].f.y; op[3] = o[p][3].f.y;
            }
        }
    }
    // last column (c = 256): duplicated value at sC2[k*520 + 512]
    if (t < 128) {
        int r = t;
        float a = 0.0f;
        #pragma unroll 8
        for (int k = 0; k < 32; ++k)
            a += sD[k*132 + r] * sC2[k*520 + 512];
        int grow = row0 + r;
        if (grow < n) outI[(size_t)grow*257 + 256] = a;
    }
}

// ------------------------- launch -----------------------------------------
extern "C" void kernel_launch(void* const* d_in, const int* in_sizes, int n_in,
                              void* d_out, int out_size)
{
    const int*   coords = (const int*)  d_in[0];
    const float* feats  = (const float*)d_in[1];
    const float* scores = (const float*)d_in[2];
    const float* Wv     = (const float*)d_in[3];
    const float* bv     = (const float*)d_in[4];
    const float* Wc     = (const float*)d_in[5];
    const float* bc     = (const float*)d_in[6];
    const float* bg     = (const float*)d_in[7];

    int n = in_sizes[0] / 4;
    if (n > NMAX) n = NMAX;

    float* out = (float*)d_out;
    long long inst = (long long)n * 257;
    int off = (int)((long long)out_size - inst);   // expect 256 (conf first)
    if (off < 0) off = 0;
    float* conf_out = (off >= KTOP) ? out : nullptr;
    float* inst_out = out + off;

    cudaFuncSetAttribute(k_main, cudaFuncAttributeMaxDynamicSharedMemorySize,
                         SM_FLTS * (int)sizeof(float));

    int nb = (n + 255) / 256;
    k_clear <<<(GCELLS + 255) / 256, 256>>>(n);
    k_fill  <<<nb, 256>>>(coords, n);
    k_peaks <<<nb, 256>>>(coords, scores, n);
    k_scan  <<<1, 256>>>();
    k_collect<<<nb, 256>>>(scores, n);
    k_sort  <<<1, 1024>>>(conf_out);
    k_owner <<<1, 256>>>(coords, scores);
    k_segsum<<<1792, 128>>>(feats);
    k_cols  <<<257, 128>>>(Wc, bc, bg);

    int mb = (n + 127) / 128;
    k_main<<<mb, 256, SM_FLTS * (int)sizeof(float)>>>(feats, Wv, bv, inst_out, n);
}

// round 6
// speedup vs baseline: 1.7800x; 1.7800x over previous
#include <cuda_runtime.h>
#include <cuda_bf16.h>
#include <cstdint>
#include <cstddef>

#define NMAX   500000
#define GQ     128
#define GCELLS (2*GQ*GQ*GQ)
#define KTOP   256
#define NBINS  4096
#define CANDMAX 4096
#define NCOLS  257
#define NPAD   264            // padded cols (33 n8 tiles)
#define NTJ    33             // n8 tiles
#define FRAGN  (NTJ*8*32)     // 8448 uint2 per matrix

// ------------------------- scratch (__device__ globals, no allocs) ---------
__device__ int                 g_grid[GCELLS];
__device__ int                 g_owner[NMAX];
__device__ unsigned char       g_peak[NMAX];
__device__ int                 g_hist[NBINS];
__device__ int                 g_thresh;
__device__ int                 g_candcnt;
__device__ int                 g_touchcnt;
__device__ unsigned long long  g_ckey[CANDMAX];
__device__ float               g_conf[KTOP];
__device__ int                 g_topidx[KTOP];
__device__ int                 g_touched[2048];
__device__ float               g_sums[KTOP*128];
__device__ float               g_counts[KTOP];
__device__ float               g_cols[NCOLS*32];
__device__ unsigned short      g_Bhi[NPAD*128];
__device__ unsigned short      g_Blo[NPAD*128];
__device__ float               g_r[NPAD];
__device__ uint2               g_fragHi[FRAGN];
__device__ uint2               g_fragLo[FRAGN];

// ------------------------- helpers ----------------------------------------
__device__ __forceinline__ uint32_t pack_bf16(float lo, float hi) {
    uint32_t r;
    asm("cvt.rn.bf16x2.f32 %0, %1, %2;" : "=r"(r) : "f"(hi), "f"(lo));
    return r;
}
__device__ __forceinline__ float bf16_lo_f(uint32_t p) {
    __nv_bfloat16 h = __ushort_as_bfloat16((unsigned short)(p & 0xFFFFu));
    return __bfloat162float(h);
}
__device__ __forceinline__ float bf16_hi_f(uint32_t p) {
    __nv_bfloat16 h = __ushort_as_bfloat16((unsigned short)(p >> 16));
    return __bfloat162float(h);
}
__device__ __forceinline__ void mma_bf16(float* c, const uint32_t* a,
                                         uint32_t b0, uint32_t b1)
{
    asm volatile(
        "mma.sync.aligned.m16n8k16.row.col.f32.bf16.bf16.f32 "
        "{%0,%1,%2,%3}, {%4,%5,%6,%7}, {%8,%9}, {%0,%1,%2,%3};"
        : "+f"(c[0]), "+f"(c[1]), "+f"(c[2]), "+f"(c[3])
        : "r"(a[0]), "r"(a[1]), "r"(a[2]), "r"(a[3]), "r"(b0), "r"(b1));
}

// ------------------------- clear ------------------------------------------
__global__ void k_clear(int n)
{
    int i = blockIdx.x * blockDim.x + threadIdx.x;
    if (i < GCELLS) g_grid[i] = -1;
    if (i < NMAX)   g_owner[i] = -1;
    if (i < NBINS)  g_hist[i]  = 0;
    if (i < KTOP*128) g_sums[i] = 0.0f;
    if (i < KTOP)   g_counts[i] = 0.0f;
    if (i == 0) { g_candcnt = 0; g_touchcnt = 0; }
}

// ------------------------- fill grid --------------------------------------
__global__ void k_fill(const int* __restrict__ coords, int n)
{
    int i = blockIdx.x * blockDim.x + threadIdx.x;
    if (i >= n) return;
    int4 c = ((const int4*)coords)[i];
    int cell = ((c.x * GQ + c.y) * GQ + c.z) * GQ + c.w;
    g_grid[cell] = i;
}

// ------------------------- peak detection + histogram ---------------------
__global__ void k_peaks(const int* __restrict__ coords,
                        const float* __restrict__ scores, int n)
{
    int i = blockIdx.x * blockDim.x + threadIdx.x;
    if (i >= n) return;
    float s = scores[i];
    bool pk = false;
    if (s > 0.1f) {
        float nm = -1e30f;
        int4 c = ((const int4*)coords)[i];
        const int dx[7] = {0, 1,-1, 0, 0, 0, 0};
        const int dy[7] = {0, 0, 0, 1,-1, 0, 0};
        const int dz[7] = {0, 0, 0, 0, 0, 1,-1};
        #pragma unroll
        for (int o = 0; o < 7; ++o) {
            int nx = c.y + dx[o], ny = c.z + dy[o], nz = c.w + dz[o];
            if (nx < 0 || nx >= GQ || ny < 0 || ny >= GQ || nz < 0 || nz >= GQ) continue;
            int cell = ((c.x * GQ + nx) * GQ + ny) * GQ + nz;
            int j = g_grid[cell];
            if (j >= 0) {
                float sj = scores[j];
                if (sj > 0.1f) nm = fmaxf(nm, sj);
            }
        }
        pk = (s >= nm - 1e-6f) && (s >= 0.5f);
    }
    g_peak[i] = pk ? 1 : 0;
    if (pk) {
        int b = (int)((s - 0.5f) * 8192.0f);
        b = b < 0 ? 0 : (b > NBINS-1 ? NBINS-1 : b);
        atomicAdd(&g_hist[b], 1);
    }
}

// ------------------------- threshold scan (1 block, 256 thr) --------------
__global__ void k_scan()
{
    __shared__ int h[NBINS];
    __shared__ int sup[64];
    int t = threadIdx.x;
    for (int i = t; i < NBINS; i += 256) h[i] = g_hist[i];
    __syncthreads();
    if (t < 64) {
        int s = 0;
        for (int m = 0; m < 64; ++m) s += h[t*64 + m];
        sup[t] = s;
    }
    __syncthreads();
    if (t == 0) {
        int total = 0;
        for (int s = 0; s < 64; ++s) total += sup[s];
        int target = total < KTOP ? total : KTOP;
        int T = 0;
        if (target > 0) {
            int acc = 0, sb = 63;
            for (; sb >= 0; --sb) {
                if (acc + sup[sb] >= target) break;
                acc += sup[sb];
            }
            for (int b = 63; b >= 0; --b) {
                acc += h[sb*64 + b];
                if (acc >= target) { T = sb*64 + b; break; }
            }
        }
        g_thresh = T;
    }
}

// ------------------------- collect candidates -----------------------------
__global__ void k_collect(const float* __restrict__ scores, int n)
{
    int i = blockIdx.x * blockDim.x + threadIdx.x;
    if (i >= n || !g_peak[i]) return;
    float s = scores[i];
    int b = (int)((s - 0.5f) * 8192.0f);
    b = b < 0 ? 0 : (b > NBINS-1 ? NBINS-1 : b);
    if (b >= g_thresh) {
        int pos = atomicAdd(&g_candcnt, 1);
        if (pos < CANDMAX) {
            unsigned long long key =
                ((unsigned long long)__float_as_uint(s) << 32)
              | (unsigned long long)(0xFFFFFFFFu - (unsigned)i);
            g_ckey[pos] = key;
        }
    }
}

// ------------------------- bitonic top-256 (1 block, 1024 thr) ------------
__global__ void k_sort(float* conf_out)
{
    __shared__ unsigned long long sk[CANDMAX];
    int t = threadIdx.x;
    int cnt = g_candcnt;
    if (cnt > CANDMAX) cnt = CANDMAX;
    for (int i = t; i < CANDMAX; i += 1024)
        sk[i] = (i < cnt) ? g_ckey[i] : 0ULL;
    __syncthreads();
    for (int k = 2; k <= CANDMAX; k <<= 1) {
        for (int j = k >> 1; j > 0; j >>= 1) {
            for (int i = t; i < CANDMAX; i += 1024) {
                int ixj = i ^ j;
                if (ixj > i) {
                    unsigned long long a = sk[i], b = sk[ixj];
                    bool sw = ((i & k) == 0) ? (a < b) : (a > b);
                    if (sw) { sk[i] = b; sk[ixj] = a; }
                }
            }
            __syncthreads();
        }
    }
    if (t < KTOP) {
        bool valid = t < cnt;
        unsigned long long key = sk[t];
        float sc = valid ? __uint_as_float((unsigned)(key >> 32)) : 0.0f;
        g_conf[t] = sc;
        g_topidx[t] = valid ? (int)(0xFFFFFFFFu - (unsigned)(key & 0xFFFFFFFFULL)) : -1;
        if (conf_out) conf_out[t] = sc;
    }
}

// ------------------------- owner assignment (1 block, 256 thr) ------------
__global__ void k_owner(const int* __restrict__ coords,
                        const float* __restrict__ scores)
{
    int k = threadIdx.x;
    if (k >= KTOP) return;
    int p = g_topidx[k];
    if (p < 0) return;
    int4 c = ((const int4*)coords)[p];
    const int dx[7] = {0, 1,-1, 0, 0, 0, 0};
    const int dy[7] = {0, 0, 0, 1,-1, 0, 0};
    const int dz[7] = {0, 0, 0, 0, 0, 1,-1};
    #pragma unroll
    for (int o = 0; o < 7; ++o) {
        int nx = c.y + dx[o], ny = c.z + dy[o], nz = c.w + dz[o];
        if (nx < 0 || nx >= GQ || ny < 0 || ny >= GQ || nz < 0 || nz >= GQ) continue;
        int cell = ((c.x * GQ + nx) * GQ + ny) * GQ + nz;
        int j = g_grid[cell];
        if (j >= 0 && scores[j] > 0.1f) {
            int old = atomicMax(&g_owner[j], k);
            if (old == -1) {
                int pos = atomicAdd(&g_touchcnt, 1);
                g_touched[pos] = j;
            }
        }
    }
}

// ------------------------- segment sums -----------------------------------
__global__ void k_segsum(const float* __restrict__ feats)
{
    if ((int)blockIdx.x >= g_touchcnt) return;
    int i = g_touched[blockIdx.x];
    int o = g_owner[i];
    atomicAdd(&g_sums[o*128 + threadIdx.x], feats[(size_t)i*128 + threadIdx.x]);
    if (threadIdx.x == 0) atomicAdd(&g_counts[o], 1.0f);
}

// ------------------------- build cols (257 blocks x 128) ------------------
__global__ void k_cols(const float* __restrict__ Wc,
                       const float* __restrict__ bc,
                       const float* __restrict__ bg)
{
    int k = blockIdx.x;
    int t = threadIdx.x;
    if (k == 0) {
        if (t < 32) g_cols[t] = bg[t];
        return;
    }
    int seg = k - 1;
    __shared__ float mean[128];
    float cnt = fmaxf(g_counts[seg], 1.0f);
    mean[t] = g_sums[seg*128 + t] / cnt;
    __syncthreads();
    if (t < 32) {
        float a = bc[t];
        #pragma unroll 8
        for (int m = 0; m < 128; ++m) a += mean[m] * Wc[m*32 + t];
        g_cols[k*32 + t] = g_conf[seg] * a;
    }
}

// ------------------------- fold: B = (Wv@cols^T)^T bf16 hi/lo, r = bv@colsT
__global__ void k_prep(const float* __restrict__ Wv, const float* __restrict__ bv)
{
    int c = blockIdx.x;
    int k = threadIdx.x;
    __shared__ float colv[32];
    if (k < 32) colv[k] = (c < NCOLS) ? g_cols[c*32 + k] : 0.0f;
    __syncthreads();
    float m = 0.0f;
    #pragma unroll
    for (int d = 0; d < 32; ++d) m += Wv[k*32 + d] * colv[d];
    if (c >= NCOLS) m = 0.0f;
    __nv_bfloat16 hi = __float2bfloat16(m);
    float rem = m - __bfloat162float(hi);
    g_Bhi[c*128 + k] = __bfloat16_as_ushort(hi);
    g_Blo[c*128 + k] = __bfloat16_as_ushort(__float2bfloat16(rem));
    if (k == 0) {
        float rr = 0.0f;
        #pragma unroll
        for (int d = 0; d < 32; ++d) rr += bv[d] * colv[d];
        g_r[c] = (c < NCOLS) ? rr : 0.0f;
    }
}

// ------------------------- fragment reorder (33 blocks x 256) -------------
// frag idx = (j*8 + kt)*32 + l; thread holds n = j*8+l/4, k0 = kt*16+2*(l%4)
// uint2.x = {k0, k0+1}, uint2.y = {k0+8, k0+9}
__global__ void k_bfrag()
{
    int idx = blockIdx.x * 256 + threadIdx.x;
    if (idx >= FRAGN) return;
    int j  = idx >> 8;
    int kt = (idx >> 5) & 7;
    int l  = idx & 31;
    int nn = j*8 + (l >> 2);
    int k0 = kt*16 + 2*(l & 3);
    const unsigned short* bh = g_Bhi + nn*128;
    const unsigned short* bl = g_Blo + nn*128;
    uint2 h, lo;
    h.x  = (uint32_t)bh[k0]     | ((uint32_t)bh[k0+1] << 16);
    h.y  = (uint32_t)bh[k0+8]   | ((uint32_t)bh[k0+9] << 16);
    lo.x = (uint32_t)bl[k0]     | ((uint32_t)bl[k0+1] << 16);
    lo.y = (uint32_t)bl[k0+8]   | ((uint32_t)bl[k0+9] << 16);
    g_fragHi[idx] = h;
    g_fragLo[idx] = lo;
}

// ------------------------- persistent mma.sync GEMM -----------------------
// out[n, 257] = A[n,128] @ B^T + r, 3-term bf16 split
// smem: fragHi 67584 B | fragLo 67584 B | r 1056 B
#define SM_BH   0
#define SM_BL   67584
#define SM_R    135168
#define SM_TOT  (135168 + NPAD*4)

__global__ void __launch_bounds__(512, 1)
k_gemm(const float* __restrict__ A, float* __restrict__ outI, int n, int ntiles)
{
    extern __shared__ char smraw[];
    uint2* sBH = (uint2*)(smraw + SM_BH);
    uint2* sBL = (uint2*)(smraw + SM_BL);
    float* sR  = (float*)(smraw + SM_R);

    int t   = threadIdx.x;
    int wid = t >> 5;
    int l   = t & 31;

    for (int i = t; i < FRAGN; i += 512) {
        sBH[i] = g_fragHi[i];
        sBL[i] = g_fragLo[i];
    }
    for (int i = t; i < NPAD; i += 512) sR[i] = g_r[i];
    __syncthreads();

    int lq = l >> 2;           // 0..7
    int lr = l & 3;            // 0..3

    for (int tile = blockIdx.x; tile < ntiles; tile += gridDim.x) {
        int rowbase = tile * 256 + wid * 16;
        int r0 = rowbase + lq;
        int r1 = r0 + 8;
        bool ok0 = r0 < n, ok1 = r1 < n;

        // ---- load A fragments from global, split hi/lo ----
        uint32_t ahi[8][4], alo[8][4];
        #pragma unroll
        for (int kt = 0; kt < 8; ++kt) {
            int k0 = kt*16 + 2*lr;
            float2 p00 = make_float2(0.f, 0.f), p10 = p00, p01 = p00, p11 = p00;
            if (ok0) {
                p00 = *(const float2*)(A + (size_t)r0*128 + k0);
                p01 = *(const float2*)(A + (size_t)r0*128 + k0 + 8);
            }
            if (ok1) {
                p10 = *(const float2*)(A + (size_t)r1*128 + k0);
                p11 = *(const float2*)(A + (size_t)r1*128 + k0 + 8);
            }
            uint32_t h;
            h = pack_bf16(p00.x, p00.y); ahi[kt][0] = h;
            alo[kt][0] = pack_bf16(p00.x - bf16_lo_f(h), p00.y - bf16_hi_f(h));
            h = pack_bf16(p10.x, p10.y); ahi[kt][1] = h;
            alo[kt][1] = pack_bf16(p10.x - bf16_lo_f(h), p10.y - bf16_hi_f(h));
            h = pack_bf16(p01.x, p01.y); ahi[kt][2] = h;
            alo[kt][2] = pack_bf16(p01.x - bf16_lo_f(h), p01.y - bf16_hi_f(h));
            h = pack_bf16(p11.x, p11.y); ahi[kt][3] = h;
            alo[kt][3] = pack_bf16(p11.x - bf16_lo_f(h), p11.y - bf16_hi_f(h));
        }

        // ---- loop over 33 n8 tiles ----
        #pragma unroll 1
        for (int j = 0; j < NTJ; ++j) {
            float acc[4] = {0.f, 0.f, 0.f, 0.f};
            const uint2* pbh = sBH + j*256 + l;
            const uint2* pbl = sBL + j*256 + l;
            #pragma unroll
            for (int kt = 0; kt < 8; ++kt) {
                uint2 bh = pbh[kt*32];
                uint2 bl = pbl[kt*32];
                mma_bf16(acc, ahi[kt], bh.x, bh.y);
                mma_bf16(acc, alo[kt], bh.x, bh.y);
                mma_bf16(acc, ahi[kt], bl.x, bl.y);
            }
            int n0 = j*8 + 2*lr;
            float rx = sR[n0], ry = sR[n0 + 1];
            if (j < NTJ - 1) {
                if (ok0) {
                    float* op = outI + (size_t)r0*NCOLS + n0;
                    op[0] = acc[0] + rx; op[1] = acc[1] + ry;
                }
                if (ok1) {
                    float* op = outI + (size_t)r1*NCOLS + n0;
                    op[0] = acc[2] + rx; op[1] = acc[3] + ry;
                }
            } else {
                if (n0 == 256) {   // only col 256 valid in last tile
                    if (ok0) outI[(size_t)r0*NCOLS + 256] = acc[0] + rx;
                    if (ok1) outI[(size_t)r1*NCOLS + 256] = acc[2] + rx;
                }
            }
        }
    }
}

// ------------------------- launch -----------------------------------------
extern "C" void kernel_launch(void* const* d_in, const int* in_sizes, int n_in,
                              void* d_out, int out_size)
{
    const int*   coords = (const int*)  d_in[0];
    const float* feats  = (const float*)d_in[1];
    const float* scores = (const float*)d_in[2];
    const float* Wv     = (const float*)d_in[3];
    const float* bv     = (const float*)d_in[4];
    const float* Wc     = (const float*)d_in[5];
    const float* bc     = (const float*)d_in[6];
    const float* bg     = (const float*)d_in[7];

    int n = in_sizes[0] / 4;
    if (n > NMAX) n = NMAX;

    float* out = (float*)d_out;
    long long inst = (long long)n * NCOLS;
    int off = (int)((long long)out_size - inst);   // expect 256 (conf first)
    if (off < 0) off = 0;
    float* conf_out = (off >= KTOP) ? out : nullptr;
    float* inst_out = out + off;

    cudaFuncSetAttribute(k_gemm, cudaFuncAttributeMaxDynamicSharedMemorySize, SM_TOT);

    int nb = (n + 255) / 256;
    k_clear <<<(GCELLS + 255) / 256, 256>>>(n);
    k_fill  <<<nb, 256>>>(coords, n);
    k_peaks <<<nb, 256>>>(coords, scores, n);
    k_scan  <<<1, 256>>>();
    k_collect<<<nb, 256>>>(scores, n);
    k_sort  <<<1, 1024>>>(conf_out);
    k_owner <<<1, 256>>>(coords, scores);
    k_segsum<<<1792, 128>>>(feats);
    k_cols  <<<257, 128>>>(Wc, bc, bg);
    k_prep  <<<NPAD, 128>>>(Wv, bv);
    k_bfrag <<<NTJ, 256>>>();

    int ntiles = (n + 255) / 256;
    k_gemm<<<148, 512, SM_TOT>>>(feats, inst_out, n, ntiles);
}

// round 7
// speedup vs baseline: 2.5556x; 1.4357x over previous
#include <cuda_runtime.h>
#include <cuda_bf16.h>
#include <cstdint>
#include <cstddef>

#define NMAX   500000
#define GQ     128
#define GCELLS (2*GQ*GQ*GQ)
#define KTOP   256
#define NBINS  4096
#define CANDMAX 4096
#define NCOLS  257
#define NPAD   264            // padded cols (33 n8 tiles)
#define NTJ    33             // n8 tiles
#define WFRAGN (4*8*32)       // stage-1 B fragments (Wv): 1024 uint2
#define CFRAGN (NTJ*2*32)     // stage-2 B fragments (cols): 2112 uint2

// ------------------------- scratch (__device__ globals, no allocs) ---------
__device__ int                 g_grid[GCELLS];
__device__ int                 g_owner[NMAX];
__device__ unsigned char       g_peak[NMAX];
__device__ int                 g_hist[NBINS];
__device__ int                 g_thresh;
__device__ int                 g_candcnt;
__device__ int                 g_touchcnt;
__device__ unsigned long long  g_ckey[CANDMAX];
__device__ float               g_conf[KTOP];
__device__ int                 g_topidx[KTOP];
__device__ int                 g_touched[2048];
__device__ float               g_sums[KTOP*128];
__device__ float               g_counts[KTOP];
__device__ float               g_cols[NCOLS*32];
__device__ uint2               g_wfH[WFRAGN];
__device__ uint2               g_wfL[WFRAGN];
__device__ uint2               g_cfH[CFRAGN];
__device__ uint2               g_cfL[CFRAGN];

// ------------------------- helpers ----------------------------------------
__device__ __forceinline__ uint32_t pack_bf16(float lo, float hi) {
    uint32_t r;
    asm("cvt.rn.bf16x2.f32 %0, %1, %2;" : "=r"(r) : "f"(hi), "f"(lo));
    return r;
}
__device__ __forceinline__ float bf16_lo_f(uint32_t p) {
    __nv_bfloat16 h = __ushort_as_bfloat16((unsigned short)(p & 0xFFFFu));
    return __bfloat162float(h);
}
__device__ __forceinline__ float bf16_hi_f(uint32_t p) {
    __nv_bfloat16 h = __ushort_as_bfloat16((unsigned short)(p >> 16));
    return __bfloat162float(h);
}
__device__ __forceinline__ void mma_bf16(float* c, const uint32_t* a,
                                         uint32_t b0, uint32_t b1)
{
    asm volatile(
        "mma.sync.aligned.m16n8k16.row.col.f32.bf16.bf16.f32 "
        "{%0,%1,%2,%3}, {%4,%5,%6,%7}, {%8,%9}, {%0,%1,%2,%3};"
        : "+f"(c[0]), "+f"(c[1]), "+f"(c[2]), "+f"(c[3])
        : "r"(a[0]), "r"(a[1]), "r"(a[2]), "r"(a[3]), "r"(b0), "r"(b1));
}

// ------------------------- clear ------------------------------------------
__global__ void k_clear(int n)
{
    int i = blockIdx.x * blockDim.x + threadIdx.x;
    if (i < GCELLS) g_grid[i] = -1;
    if (i < NMAX)   g_owner[i] = -1;
    if (i < NBINS)  g_hist[i]  = 0;
    if (i < KTOP*128) g_sums[i] = 0.0f;
    if (i < KTOP)   g_counts[i] = 0.0f;
    if (i == 0) { g_candcnt = 0; g_touchcnt = 0; }
}

// ------------------------- fill grid --------------------------------------
__global__ void k_fill(const int* __restrict__ coords, int n)
{
    int i = blockIdx.x * blockDim.x + threadIdx.x;
    if (i >= n) return;
    int4 c = ((const int4*)coords)[i];
    int cell = ((c.x * GQ + c.y) * GQ + c.z) * GQ + c.w;
    g_grid[cell] = i;
}

// ------------------------- peak detection + histogram ---------------------
__global__ void k_peaks(const int* __restrict__ coords,
                        const float* __restrict__ scores, int n)
{
    int i = blockIdx.x * blockDim.x + threadIdx.x;
    if (i >= n) return;
    float s = scores[i];
    bool pk = false;
    if (s > 0.1f) {
        float nm = -1e30f;
        int4 c = ((const int4*)coords)[i];
        const int dx[7] = {0, 1,-1, 0, 0, 0, 0};
        const int dy[7] = {0, 0, 0, 1,-1, 0, 0};
        const int dz[7] = {0, 0, 0, 0, 0, 1,-1};
        #pragma unroll
        for (int o = 0; o < 7; ++o) {
            int nx = c.y + dx[o], ny = c.z + dy[o], nz = c.w + dz[o];
            if (nx < 0 || nx >= GQ || ny < 0 || ny >= GQ || nz < 0 || nz >= GQ) continue;
            int cell = ((c.x * GQ + nx) * GQ + ny) * GQ + nz;
            int j = g_grid[cell];
            if (j >= 0) {
                float sj = scores[j];
                if (sj > 0.1f) nm = fmaxf(nm, sj);
            }
        }
        pk = (s >= nm - 1e-6f) && (s >= 0.5f);
    }
    g_peak[i] = pk ? 1 : 0;
    if (pk) {
        int b = (int)((s - 0.5f) * 8192.0f);
        b = b < 0 ? 0 : (b > NBINS-1 ? NBINS-1 : b);
        atomicAdd(&g_hist[b], 1);
    }
}

// ------------------------- threshold scan (1 block, 256 thr) --------------
__global__ void k_scan()
{
    __shared__ int h[NBINS];
    __shared__ int sup[64];
    int t = threadIdx.x;
    for (int i = t; i < NBINS; i += 256) h[i] = g_hist[i];
    __syncthreads();
    if (t < 64) {
        int s = 0;
        for (int m = 0; m < 64; ++m) s += h[t*64 + m];
        sup[t] = s;
    }
    __syncthreads();
    if (t == 0) {
        int total = 0;
        for (int s = 0; s < 64; ++s) total += sup[s];
        int target = total < KTOP ? total : KTOP;
        int T = 0;
        if (target > 0) {
            int acc = 0, sb = 63;
            for (; sb >= 0; --sb) {
                if (acc + sup[sb] >= target) break;
                acc += sup[sb];
            }
            for (int b = 63; b >= 0; --b) {
                acc += h[sb*64 + b];
                if (acc >= target) { T = sb*64 + b; break; }
            }
        }
        g_thresh = T;
    }
}

// ------------------------- collect candidates -----------------------------
__global__ void k_collect(const float* __restrict__ scores, int n)
{
    int i = blockIdx.x * blockDim.x + threadIdx.x;
    if (i >= n || !g_peak[i]) return;
    float s = scores[i];
    int b = (int)((s - 0.5f) * 8192.0f);
    b = b < 0 ? 0 : (b > NBINS-1 ? NBINS-1 : b);
    if (b >= g_thresh) {
        int pos = atomicAdd(&g_candcnt, 1);
        if (pos < CANDMAX) {
            unsigned long long key =
                ((unsigned long long)__float_as_uint(s) << 32)
              | (unsigned long long)(0xFFFFFFFFu - (unsigned)i);
            g_ckey[pos] = key;
        }
    }
}

// ------------------------- bitonic top-256 (1 block, 1024 thr) ------------
__global__ void k_sort(float* conf_out)
{
    __shared__ unsigned long long sk[CANDMAX];
    int t = threadIdx.x;
    int cnt = g_candcnt;
    if (cnt > CANDMAX) cnt = CANDMAX;
    for (int i = t; i < CANDMAX; i += 1024)
        sk[i] = (i < cnt) ? g_ckey[i] : 0ULL;
    __syncthreads();
    for (int k = 2; k <= CANDMAX; k <<= 1) {
        for (int j = k >> 1; j > 0; j >>= 1) {
            for (int i = t; i < CANDMAX; i += 1024) {
                int ixj = i ^ j;
                if (ixj > i) {
                    unsigned long long a = sk[i], b = sk[ixj];
                    bool sw = ((i & k) == 0) ? (a < b) : (a > b);
                    if (sw) { sk[i] = b; sk[ixj] = a; }
                }
            }
            __syncthreads();
        }
    }
    if (t < KTOP) {
        bool valid = t < cnt;
        unsigned long long key = sk[t];
        float sc = valid ? __uint_as_float((unsigned)(key >> 32)) : 0.0f;
        g_conf[t] = sc;
        g_topidx[t] = valid ? (int)(0xFFFFFFFFu - (unsigned)(key & 0xFFFFFFFFULL)) : -1;
        if (conf_out) conf_out[t] = sc;
    }
}

// ------------------------- owner assignment (1 block, 256 thr) ------------
__global__ void k_owner(const int* __restrict__ coords,
                        const float* __restrict__ scores)
{
    int k = threadIdx.x;
    if (k >= KTOP) return;
    int p = g_topidx[k];
    if (p < 0) return;
    int4 c = ((const int4*)coords)[p];
    const int dx[7] = {0, 1,-1, 0, 0, 0, 0};
    const int dy[7] = {0, 0, 0, 1,-1, 0, 0};
    const int dz[7] = {0, 0, 0, 0, 0, 1,-1};
    #pragma unroll
    for (int o = 0; o < 7; ++o) {
        int nx = c.y + dx[o], ny = c.z + dy[o], nz = c.w + dz[o];
        if (nx < 0 || nx >= GQ || ny < 0 || ny >= GQ || nz < 0 || nz >= GQ) continue;
        int cell = ((c.x * GQ + nx) * GQ + ny) * GQ + nz;
        int j = g_grid[cell];
        if (j >= 0 && scores[j] > 0.1f) {
            int old = atomicMax(&g_owner[j], k);
            if (old == -1) {
                int pos = atomicAdd(&g_touchcnt, 1);
                g_touched[pos] = j;
            }
        }
    }
}

// ------------------------- segment sums -----------------------------------
__global__ void k_segsum(const float* __restrict__ feats)
{
    if ((int)blockIdx.x >= g_touchcnt) return;
    int i = g_touched[blockIdx.x];
    int o = g_owner[i];
    atomicAdd(&g_sums[o*128 + threadIdx.x], feats[(size_t)i*128 + threadIdx.x]);
    if (threadIdx.x == 0) atomicAdd(&g_counts[o], 1.0f);
}

// ------------------------- build cols (257 blocks x 128) ------------------
__global__ void k_cols(const float* __restrict__ Wc,
                       const float* __restrict__ bc,
                       const float* __restrict__ bg)
{
    int k = blockIdx.x;
    int t = threadIdx.x;
    if (k == 0) {
        if (t < 32) g_cols[t] = bg[t];
        return;
    }
    int seg = k - 1;
    __shared__ float mean[128];
    float cnt = fmaxf(g_counts[seg], 1.0f);
    mean[t] = g_sums[seg*128 + t] / cnt;
    __syncthreads();
    if (t < 32) {
        float a = bc[t];
        #pragma unroll 8
        for (int m = 0; m < 128; ++m) a += mean[m] * Wc[m*32 + t];
        g_cols[k*32 + t] = g_conf[seg] * a;
    }
}

// ------------------------- Wv fragments (stage-1 B, hi/lo) ----------------
// frag idx = (j*8 + kt)*32 + l; d = j*8 + l/4, k0 = kt*16 + 2*(l%4)
// B[n=d][k] = Wv[k][d]
__global__ void k_wvfrag(const float* __restrict__ Wv)
{
    int idx = blockIdx.x * 256 + threadIdx.x;
    if (idx >= WFRAGN) return;
    int l  = idx & 31;
    int kt = (idx >> 5) & 7;
    int j  = idx >> 8;
    int d  = j*8 + (l >> 2);
    int k0 = kt*16 + 2*(l & 3);
    float w0 = Wv[(k0  )*32 + d], w1 = Wv[(k0+1)*32 + d];
    float w2 = Wv[(k0+8)*32 + d], w3 = Wv[(k0+9)*32 + d];
    uint32_t hx = pack_bf16(w0, w1), hy = pack_bf16(w2, w3);
    uint32_t lx = pack_bf16(w0 - bf16_lo_f(hx), w1 - bf16_hi_f(hx));
    uint32_t ly = pack_bf16(w2 - bf16_lo_f(hy), w3 - bf16_hi_f(hy));
    g_wfH[idx] = make_uint2(hx, hy);
    g_wfL[idx] = make_uint2(lx, ly);
}

// ------------------------- cols fragments (stage-2 B, hi/lo) --------------
// frag idx = (j*2 + kt)*32 + l; c = j*8 + l/4, k0 = kt*16 + 2*(l%4) (k = d)
// B[n=c][k=d] = cols[c][d]
__global__ void k_cfrag()
{
    int idx = blockIdx.x * 256 + threadIdx.x;
    if (idx >= CFRAGN) return;
    int l  = idx & 31;
    int kt = (idx >> 5) & 1;
    int j  = idx >> 6;
    int c  = j*8 + (l >> 2);
    int k0 = kt*16 + 2*(l & 3);
    float w0 = 0.f, w1 = 0.f, w2 = 0.f, w3 = 0.f;
    if (c < NCOLS) {
        const float* row = g_cols + c*32;
        w0 = row[k0]; w1 = row[k0+1]; w2 = row[k0+8]; w3 = row[k0+9];
    }
    uint32_t hx = pack_bf16(w0, w1), hy = pack_bf16(w2, w3);
    uint32_t lx = pack_bf16(w0 - bf16_lo_f(hx), w1 - bf16_hi_f(hx));
    uint32_t ly = pack_bf16(w2 - bf16_lo_f(hy), w3 - bf16_hi_f(hy));
    g_cfH[idx] = make_uint2(hx, hy);
    g_cfL[idx] = make_uint2(lx, ly);
}

// ------------------------- persistent two-stage mma.sync GEMM -------------
// stage1: desc = A@Wv + bv (reg-resident C-frags -> A-frags, no smem xpose)
// stage2: out  = desc @ cols^T
// smem: wfH 8192 | wfL 8192 | cfH 16896 | cfL 16896 | bv 128  = 50304 B
#define SM_WH   0
#define SM_WL   8192
#define SM_CH   16384
#define SM_CL   33280
#define SM_BV   50176
#define SM_TOT  50304

__global__ void __launch_bounds__(512, 1)
k_gemm(const float* __restrict__ A, const float* __restrict__ bv,
       float* __restrict__ outI, int n, int ntiles)
{
    extern __shared__ char smraw[];
    uint2* sWH = (uint2*)(smraw + SM_WH);
    uint2* sWL = (uint2*)(smraw + SM_WL);
    uint2* sCH = (uint2*)(smraw + SM_CH);
    uint2* sCL = (uint2*)(smraw + SM_CL);
    float* sBV = (float*)(smraw + SM_BV);

    int t   = threadIdx.x;
    int wid = t >> 5;
    int l   = t & 31;

    for (int i = t; i < WFRAGN; i += 512) { sWH[i] = g_wfH[i]; sWL[i] = g_wfL[i]; }
    for (int i = t; i < CFRAGN; i += 512) { sCH[i] = g_cfH[i]; sCL[i] = g_cfL[i]; }
    if (t < 32) sBV[t] = bv[t];
    __syncthreads();

    int lq = l >> 2;           // 0..7
    int lr = l & 3;            // 0..3

    for (int tile = blockIdx.x; tile < ntiles; tile += gridDim.x) {
        int rowbase = tile * 256 + wid * 16;
        int r0 = rowbase + lq;
        int r1 = r0 + 8;
        bool ok0 = r0 < n, ok1 = r1 < n;

        // ---- load A fragments from global, split hi/lo ----
        uint32_t ahi[8][4], alo[8][4];
        #pragma unroll
        for (int kt = 0; kt < 8; ++kt) {
            int k0 = kt*16 + 2*lr;
            float2 p00 = make_float2(0.f, 0.f), p10 = p00, p01 = p00, p11 = p00;
            if (ok0) {
                p00 = *(const float2*)(A + (size_t)r0*128 + k0);
                p01 = *(const float2*)(A + (size_t)r0*128 + k0 + 8);
            }
            if (ok1) {
                p10 = *(const float2*)(A + (size_t)r1*128 + k0);
                p11 = *(const float2*)(A + (size_t)r1*128 + k0 + 8);
            }
            uint32_t h;
            h = pack_bf16(p00.x, p00.y); ahi[kt][0] = h;
            alo[kt][0] = pack_bf16(p00.x - bf16_lo_f(h), p00.y - bf16_hi_f(h));
            h = pack_bf16(p10.x, p10.y); ahi[kt][1] = h;
            alo[kt][1] = pack_bf16(p10.x - bf16_lo_f(h), p10.y - bf16_hi_f(h));
            h = pack_bf16(p01.x, p01.y); ahi[kt][2] = h;
            alo[kt][2] = pack_bf16(p01.x - bf16_lo_f(h), p01.y - bf16_hi_f(h));
            h = pack_bf16(p11.x, p11.y); ahi[kt][3] = h;
            alo[kt][3] = pack_bf16(p11.x - bf16_lo_f(h), p11.y - bf16_hi_f(h));
        }

        // ---- stage 1: desc = A @ Wv (4 n8-tiles over d) ----
        float dsc[4][4];
        #pragma unroll
        for (int j = 0; j < 4; ++j) {
            float acc[4] = {0.f, 0.f, 0.f, 0.f};
            #pragma unroll
            for (int kt = 0; kt < 8; ++kt) {
                uint2 bh = sWH[(j*8 + kt)*32 + l];
                uint2 bl = sWL[(j*8 + kt)*32 + l];
                mma_bf16(acc, ahi[kt], bh.x, bh.y);
                mma_bf16(acc, alo[kt], bh.x, bh.y);
                mma_bf16(acc, ahi[kt], bl.x, bl.y);
            }
            dsc[j][0] = acc[0]; dsc[j][1] = acc[1];
            dsc[j][2] = acc[2]; dsc[j][3] = acc[3];
        }

        // ---- add bv, split, compose into stage-2 A fragments ----
        // a2[kt][0]=(row lq, d=16kt+2lr..): from dsc[2kt]; a2[kt][2..3]: dsc[2kt+1]
        uint32_t dhi[2][4], dlo[2][4];
        #pragma unroll
        for (int kt = 0; kt < 2; ++kt) {
            #pragma unroll
            for (int hfl = 0; hfl < 2; ++hfl) {
                int j = 2*kt + hfl;
                float b0 = sBV[j*8 + 2*lr];
                float b1 = sBV[j*8 + 2*lr + 1];
                float v0 = dsc[j][0] + b0, v1 = dsc[j][1] + b1;
                float v2 = dsc[j][2] + b0, v3 = dsc[j][3] + b1;
                uint32_t h01 = pack_bf16(v0, v1);
                uint32_t h23 = pack_bf16(v2, v3);
                dhi[kt][2*hfl+0] = h01;
                dhi[kt][2*hfl+1] = h23;
                dlo[kt][2*hfl+0] = pack_bf16(v0 - bf16_lo_f(h01), v1 - bf16_hi_f(h01));
                dlo[kt][2*hfl+1] = pack_bf16(v2 - bf16_lo_f(h23), v3 - bf16_hi_f(h23));
            }
        }

        // ---- stage 2: out = desc @ cols^T (33 n8-tiles) ----
        #pragma unroll 1
        for (int j = 0; j < NTJ; ++j) {
            float acc[4] = {0.f, 0.f, 0.f, 0.f};
            #pragma unroll
            for (int kt = 0; kt < 2; ++kt) {
                uint2 bh = sCH[(j*2 + kt)*32 + l];
                uint2 bl = sCL[(j*2 + kt)*32 + l];
                mma_bf16(acc, dhi[kt], bh.x, bh.y);
                mma_bf16(acc, dlo[kt], bh.x, bh.y);
                mma_bf16(acc, dhi[kt], bl.x, bl.y);
            }
            int n0 = j*8 + 2*lr;
            if (j < NTJ - 1) {
                if (ok0) {
                    float* op = outI + (size_t)r0*NCOLS + n0;
                    op[0] = acc[0]; op[1] = acc[1];
                }
                if (ok1) {
                    float* op = outI + (size_t)r1*NCOLS + n0;
                    op[0] = acc[2]; op[1] = acc[3];
                }
            } else {
                if (n0 == 256) {   // only col 256 valid in last tile
                    if (ok0) outI[(size_t)r0*NCOLS + 256] = acc[0];
                    if (ok1) outI[(size_t)r1*NCOLS + 256] = acc[2];
                }
            }
        }
    }
}

// ------------------------- launch -----------------------------------------
extern "C" void kernel_launch(void* const* d_in, const int* in_sizes, int n_in,
                              void* d_out, int out_size)
{
    const int*   coords = (const int*)  d_in[0];
    const float* feats  = (const float*)d_in[1];
    const float* scores = (const float*)d_in[2];
    const float* Wv     = (const float*)d_in[3];
    const float* bv     = (const float*)d_in[4];
    const float* Wc     = (const float*)d_in[5];
    const float* bc     = (const float*)d_in[6];
    const float* bg     = (const float*)d_in[7];

    int n = in_sizes[0] / 4;
    if (n > NMAX) n = NMAX;

    float* out = (float*)d_out;
    long long inst = (long long)n * NCOLS;
    int off = (int)((long long)out_size - inst);   // expect 256 (conf first)
    if (off < 0) off = 0;
    float* conf_out = (off >= KTOP) ? out : nullptr;
    float* inst_out = out + off;

    cudaFuncSetAttribute(k_gemm, cudaFuncAttributeMaxDynamicSharedMemorySize, SM_TOT);

    int nb = (n + 255) / 256;
    k_clear <<<(GCELLS + 255) / 256, 256>>>(n);
    k_fill  <<<nb, 256>>>(coords, n);
    k_peaks <<<nb, 256>>>(coords, scores, n);
    k_scan  <<<1, 256>>>();
    k_collect<<<nb, 256>>>(scores, n);
    k_sort  <<<1, 1024>>>(conf_out);
    k_owner <<<1, 256>>>(coords, scores);
    k_segsum<<<1792, 128>>>(feats);
    k_cols  <<<257, 128>>>(Wc, bc, bg);
    k_wvfrag<<<(WFRAGN + 255)/256, 256>>>(Wv);
    k_cfrag <<<(CFRAGN + 255)/256, 256>>>();

    int ntiles = (n + 255) / 256;
    k_gemm<<<148, 512, SM_TOT>>>(feats, bv, inst_out, n, ntiles);
}